// round 13
// baseline (speedup 1.0000x reference)
#include <cuda_runtime.h>
#include <math.h>

#define NC   256
#define HW   16384
#define NP   320
#define TAUF 20.0f
#define EPSF 1e-4f
#define KB   16

// Scratch (device globals — no allocation allowed)
__device__ float g_protos[NP * NC];   // pooled protos [p][c]
__device__ float g_pnT[NC * NP];      // normalized protos transposed [c][p]

// ---------------------------------------------------------------------------
// Kernel A: 16x16 average pool of sup_x -> protos_raw[p][c], p = s*64+gy*8+gx
// grid (8 gy, 256 c, 5 s), block 128 = 4 warps; float4 loads (MLP 4/thread).
// warp w covers rows {w, w+4, w+8, w+12}; lane l covers cols 4l..4l+3.
// ---------------------------------------------------------------------------
__global__ void pool_kernel(const float* __restrict__ sup)
{
    __shared__ float4 sm[4][32];
    int gy = blockIdx.x, c = blockIdx.y, s = blockIdx.z;
    const float* base = sup + ((size_t)(s * NC + c) * 128 + gy * 16) * 128;
    int w = threadIdx.x >> 5, l = threadIdx.x & 31;

    float4 acc = make_float4(0.f, 0.f, 0.f, 0.f);
#pragma unroll
    for (int r = 0; r < 4; r++) {
        float4 v = *(const float4*)&base[(w + r * 4) * 128 + l * 4];
        acc.x += v.x; acc.y += v.y; acc.z += v.z; acc.w += v.w;
    }
    sm[w][l] = acc;
    __syncthreads();
    if (w == 0) {
        float4 t0 = sm[0][l], t1 = sm[1][l], t2 = sm[2][l], t3 = sm[3][l];
        float sc = (t0.x + t1.x + t2.x + t3.x) + (t0.y + t1.y + t2.y + t3.y)
                 + (t0.z + t1.z + t2.z + t3.z) + (t0.w + t1.w + t2.w + t3.w);
        // reduce 4-lane groups (16 cols each) -> 8 grid cells
        sc += __shfl_down_sync(0xffffffffu, sc, 2, 4);
        sc += __shfl_down_sync(0xffffffffu, sc, 1, 4);
        if ((l & 3) == 0)
            g_protos[(s * 64 + gy * 8 + (l >> 2)) * NC + c] = sc * (1.0f / 256.0f);
    }
}

// ---------------------------------------------------------------------------
// Kernel B: center over channels + L2-normalize, store transposed [c][p]
// grid 320, block 256
// ---------------------------------------------------------------------------
__global__ void proto_norm_kernel()
{
    __shared__ float red[8];
    int p = blockIdx.x, c = threadIdx.x;
    float v = g_protos[p * NC + c];

    float t = v;
#pragma unroll
    for (int o = 16; o; o >>= 1) t += __shfl_xor_sync(0xffffffffu, t, o);
    if ((c & 31) == 0) red[c >> 5] = t;
    __syncthreads();
    float tot = 0.f;
#pragma unroll
    for (int i = 0; i < 8; i++) tot += red[i];
    float mean = tot * (1.0f / 256.0f);
    float ctr = v - mean;
    __syncthreads();

    t = ctr * ctr;
#pragma unroll
    for (int o = 16; o; o >>= 1) t += __shfl_xor_sync(0xffffffffu, t, o);
    if ((c & 31) == 0) red[c >> 5] = t;
    __syncthreads();
    tot = 0.f;
#pragma unroll
    for (int i = 0; i < 8; i++) tot += red[i];

    float inv = 1.0f / fmaxf(sqrtf(tot), EPSF);
    g_pnT[c * NP + p] = ctr * inv;
}

// ---------------------------------------------------------------------------
// Kernel D: fused GEMM (64 px x 320 protos x 256 ch) + qstat + softmax/argmax
//           + expected value. Packed f32x2 FMAs with:
//   - Q stored PRE-DUPLICATED in smem as u64 {v,v} pairs (built once at
//     staging: 64 movs/thread total vs 1024 when packing in the inner loop);
//     inner loop a-operands come from 2 LDS.128.
//   - FFMA2s grouped so 4 consecutive share the SAME b operand -> .reuse
//     drops b from the RF-bank distinct set (banking rt 3 -> ~2).
// Query stats (qinv) computed from the same staging loads.
// Proto interleave: lane nx owns protos {nx*4 + 64*j4 + jj} -> conflict-free
// LDS.128. __launch_bounds__(256,2): 2 blocks/SM, grid 256 in one wave.
// pro_n is exactly zero-mean over channels, so raw qry works.
// ---------------------------------------------------------------------------
__global__ __launch_bounds__(256, 2) void main_kernel(const float* __restrict__ qry,
                                                      float* __restrict__ out)
{
    __shared__ __align__(16) unsigned long long sQd[KB][64];  // 8 KB ({v,v} pairs)
    __shared__ __align__(16) float sP[KB][320];               // 20 KB

    int tid = threadIdx.x;
    int m0  = blockIdx.x * 64;
    int nx  = tid & 15;     // proto group (interleaved)
    int my  = tid >> 4;     // pixel group: pixels [my*4, my*4+4)

    // packed (f32,f32) accumulators: pixel i, proto pair j2
    unsigned long long acc2[4][10];
#pragma unroll
    for (int i = 0; i < 4; i++)
#pragma unroll
        for (int j = 0; j < 10; j++) acc2[i][j] = 0ull;

    // per-thread query stats partials: 4 pixels, 16 channels (one row/chunk)
    float4 s4  = make_float4(0.f, 0.f, 0.f, 0.f);
    float4 ss4 = make_float4(0.f, 0.f, 0.f, 0.f);

    for (int kb = 0; kb < NC; kb += KB) {
        // stage Q chunk: 16 x 64 floats, one float4 per thread, duplicated
        {
            int row = tid >> 4, col = (tid & 15) * 4;
            float4 v = *(const float4*)&qry[(size_t)(kb + row) * HW + m0 + col];
            s4.x += v.x; s4.y += v.y; s4.z += v.z; s4.w += v.w;
            ss4.x += v.x * v.x; ss4.y += v.y * v.y;
            ss4.z += v.z * v.z; ss4.w += v.w * v.w;
            ulonglong2 q01, q23;
            asm("mov.b64 %0, {%1, %1};" : "=l"(q01.x) : "f"(v.x));
            asm("mov.b64 %0, {%1, %1};" : "=l"(q01.y) : "f"(v.y));
            asm("mov.b64 %0, {%1, %1};" : "=l"(q23.x) : "f"(v.z));
            asm("mov.b64 %0, {%1, %1};" : "=l"(q23.y) : "f"(v.w));
            *(ulonglong2*)&sQd[row][col]     = q01;
            *(ulonglong2*)&sQd[row][col + 2] = q23;
        }
        // stage P chunk: 16 x 320 floats = 1280 float4 (5 per thread)
#pragma unroll
        for (int i = 0; i < 5; i++) {
            int idx4 = tid + i * 256;
            int k  = idx4 / 80;
            int pp = (idx4 - k * 80) * 4;
            *(float4*)&sP[k][pp] =
                *(const float4*)&g_pnT[(size_t)(kb + k) * NP + pp];
        }
        __syncthreads();

#pragma unroll
        for (int k = 0; k < KB; k++) {
            ulonglong2 A01 = *(const ulonglong2*)&sQd[k][my * 4];
            ulonglong2 A23 = *(const ulonglong2*)&sQd[k][my * 4 + 2];
#pragma unroll
            for (int j4 = 0; j4 < 5; j4++) {
                ulonglong2 b2 = *(const ulonglong2*)&sP[k][nx * 4 + j4 * 64];
                // group by shared b -> slot-2 .reuse -> lower RF-bank rt
                asm("fma.rn.f32x2 %0, %1, %2, %0;" : "+l"(acc2[0][j4*2  ]) : "l"(A01.x), "l"(b2.x));
                asm("fma.rn.f32x2 %0, %1, %2, %0;" : "+l"(acc2[1][j4*2  ]) : "l"(A01.y), "l"(b2.x));
                asm("fma.rn.f32x2 %0, %1, %2, %0;" : "+l"(acc2[2][j4*2  ]) : "l"(A23.x), "l"(b2.x));
                asm("fma.rn.f32x2 %0, %1, %2, %0;" : "+l"(acc2[3][j4*2  ]) : "l"(A23.y), "l"(b2.x));
                asm("fma.rn.f32x2 %0, %1, %2, %0;" : "+l"(acc2[0][j4*2+1]) : "l"(A01.x), "l"(b2.y));
                asm("fma.rn.f32x2 %0, %1, %2, %0;" : "+l"(acc2[1][j4*2+1]) : "l"(A01.y), "l"(b2.y));
                asm("fma.rn.f32x2 %0, %1, %2, %0;" : "+l"(acc2[2][j4*2+1]) : "l"(A23.x), "l"(b2.y));
                asm("fma.rn.f32x2 %0, %1, %2, %0;" : "+l"(acc2[3][j4*2+1]) : "l"(A23.y), "l"(b2.y));
            }
        }
        __syncthreads();
    }

    // ---- query-stat reduction (reuse sP memory; all compute reads done) ----
    float2* pr  = (float2*)&sP[0][0];          // [16 rowg][16 colg][4 px] float2
    float*  sqi = (float*)((char*)pr + 8192);  // 64 floats: qinv*TAU per pixel
    {
        int base = (my * 16 + nx) * 4;
        pr[base + 0] = make_float2(s4.x, ss4.x);
        pr[base + 1] = make_float2(s4.y, ss4.y);
        pr[base + 2] = make_float2(s4.z, ss4.z);
        pr[base + 3] = make_float2(s4.w, ss4.w);
    }
    __syncthreads();
    if (tid < 64) {
        int cg = tid >> 2, j = tid & 3;
        float s = 0.f, ss = 0.f;
#pragma unroll
        for (int r = 0; r < 16; r++) {
            float2 t = pr[(r * 16 + cg) * 4 + j];
            s += t.x; ss += t.y;
        }
        float var = ss - s * s * (1.0f / 256.0f);
        sqi[tid] = TAUF / fmaxf(sqrtf(fmaxf(var, 0.f)), EPSF);
    }
    __syncthreads();

    // ---- epilogue: scale, softmax-weighted mean (== pred_grid), argmax ----
    // pair j2 = j4*2+h holds protos nx*4 + j4*64 + h*2 + {0,1};
    // d[j], j=j2*2+bit -> pidx = nx*4 + (j>>2)*64 + (j&3), ascending in j.
#pragma unroll
    for (int ii = 0; ii < 4; ii++) {
        int m = m0 + my * 4 + ii;
        float sc = sqi[my * 4 + ii];

        float d[20];
#pragma unroll
        for (int j2 = 0; j2 < 10; j2++) {
            float lo, hi;
            asm("mov.b64 {%0, %1}, %2;" : "=f"(lo), "=f"(hi) : "l"(acc2[ii][j2]));
            d[j2 * 2 + 0] = lo * sc;
            d[j2 * 2 + 1] = hi * sc;
        }
        float vmax = -1e30f; int vidx = 0;
#pragma unroll
        for (int j = 0; j < 20; j++) {
            int pidx = nx * 4 + (j >> 2) * 64 + (j & 3);
            if (d[j] > vmax) { vmax = d[j]; vidx = pidx; }
        }
#pragma unroll
        for (int o = 8; o; o >>= 1) {
            float om = __shfl_xor_sync(0xffffffffu, vmax, o, 16);
            int   oi = __shfl_xor_sync(0xffffffffu, vidx, o, 16);
            if (om > vmax || (om == vmax && oi < vidx)) { vmax = om; vidx = oi; }
        }
        float se = 0.f, sn = 0.f;
#pragma unroll
        for (int j = 0; j < 20; j++) {
            float e = __expf(d[j] - vmax);
            se += e; sn += e * d[j];
        }
#pragma unroll
        for (int o = 8; o; o >>= 1) {
            se += __shfl_xor_sync(0xffffffffu, se, o, 16);
            sn += __shfl_xor_sync(0xffffffffu, sn, o, 16);
        }
        if (nx == 0) {
            out[m]      = sn / se;        // pred_grid
            out[HW + m] = (float)vidx;    // debug_assign
        }
    }
}

// ---------------------------------------------------------------------------
extern "C" void kernel_launch(void* const* d_in, const int* in_sizes, int n_in,
                              void* d_out, int out_size)
{
    const float* qry = (const float*)d_in[0];   // (1,1,256,128,128)
    const float* sup = (const float*)d_in[1];   // (1,5,1,256,128,128)
    // d_in[2] (sup_y) and d_in[3] (thresh) are dead in the reference.
    float* out = (float*)d_out;                 // [pred_grid | debug_assign]

    pool_kernel<<<dim3(8, 256, 5), 128>>>(sup);
    proto_norm_kernel<<<320, 256>>>();
    main_kernel<<<256, 256>>>(qry, out);
}

// round 14
// speedup vs baseline: 1.1308x; 1.1308x over previous
#include <cuda_runtime.h>
#include <math.h>

#define NC   256
#define HW   16384
#define NP   320
#define TAUF 20.0f
#define EPSF 1e-4f
#define KB   32

// Scratch (device globals — no allocation allowed)
__device__ float g_protos[NP * NC];   // pooled protos [p][c]
__device__ float g_pnT[NC * NP];      // normalized protos transposed [c][p]

// ---------------------------------------------------------------------------
// Kernel A: 16x16 average pool. One block per (c, s) plane (128x128 floats).
// 256 threads x 16 coalesced LDG.128 (idx4 = tid + 256*i) -> MLP=16.
// For thread tid: col4 = tid&31 (fixed -> gx = col4>>2 fixed), row = tid>>5
// + 8*i -> gy = i>>1 exactly. 8 partials/thread; smem [8][256] transposed,
// conflict-free both phases; 64 threads emit the 8x8 cells.
// ---------------------------------------------------------------------------
__global__ __launch_bounds__(256) void pool_kernel(const float* __restrict__ sup)
{
    __shared__ float sm[8][256];
    int c = blockIdx.x, s = blockIdx.y;
    const float4* plane = (const float4*)(sup + (size_t)(s * NC + c) * HW);
    int t = threadIdx.x;

    float4 p[8];
#pragma unroll
    for (int g = 0; g < 8; g++) p[g] = make_float4(0.f, 0.f, 0.f, 0.f);
#pragma unroll
    for (int i = 0; i < 16; i++) {
        float4 v = plane[t + 256 * i];
        int g = i >> 1;
        p[g].x += v.x; p[g].y += v.y; p[g].z += v.z; p[g].w += v.w;
    }
#pragma unroll
    for (int g = 0; g < 8; g++)
        sm[g][t] = (p[g].x + p[g].y) + (p[g].z + p[g].w);
    __syncthreads();

    if (t < 64) {
        int gy = t >> 3, gx = t & 7;
        float acc = 0.f;
#pragma unroll
        for (int w = 0; w < 8; w++)
#pragma unroll
            for (int l4 = 0; l4 < 4; l4++)
                acc += sm[gy][w * 32 + gx * 4 + l4];
        g_protos[(s * 64 + gy * 8 + gx) * NC + c] = acc * (1.0f / 256.0f);
    }
}

// ---------------------------------------------------------------------------
// Kernel B: center over channels + L2-normalize, store transposed [c][p]
// grid 320, block 256
// ---------------------------------------------------------------------------
__global__ void proto_norm_kernel()
{
    __shared__ float red[8];
    int p = blockIdx.x, c = threadIdx.x;
    float v = g_protos[p * NC + c];

    float t = v;
#pragma unroll
    for (int o = 16; o; o >>= 1) t += __shfl_xor_sync(0xffffffffu, t, o);
    if ((c & 31) == 0) red[c >> 5] = t;
    __syncthreads();
    float tot = 0.f;
#pragma unroll
    for (int i = 0; i < 8; i++) tot += red[i];
    float mean = tot * (1.0f / 256.0f);
    float ctr = v - mean;
    __syncthreads();

    t = ctr * ctr;
#pragma unroll
    for (int o = 16; o; o >>= 1) t += __shfl_xor_sync(0xffffffffu, t, o);
    if ((c & 31) == 0) red[c >> 5] = t;
    __syncthreads();
    tot = 0.f;
#pragma unroll
    for (int i = 0; i < 8; i++) tot += red[i];

    float inv = 1.0f / fmaxf(sqrtf(tot), EPSF);
    g_pnT[c * NP + p] = ctr * inv;
}

// ---------------------------------------------------------------------------
// Kernel D (R11 version — best measured): fused GEMM (64 px x 320 protos x
// 256 ch) + qstat + softmax/argmax + expected value. Packed f32x2 FMAs,
// in-loop a-packing, b-shared grouping; KB=32. 2 blocks/SM, one wave.
// pro_n is exactly zero-mean over channels, so raw qry works.
// ---------------------------------------------------------------------------
__global__ __launch_bounds__(256, 2) void main_kernel(const float* __restrict__ qry,
                                                      float* __restrict__ out)
{
    __shared__ __align__(16) float sQ[KB][64];    // 8 KB
    __shared__ __align__(16) float sP[KB][320];   // 40 KB  (total 48 KB)

    int tid = threadIdx.x;
    int m0  = blockIdx.x * 64;
    int nx  = tid & 15;     // proto group (interleaved)
    int my  = tid >> 4;     // pixel group: pixels [my*4, my*4+4)

    // packed (f32,f32) accumulators: pixel i, proto pair j2
    unsigned long long acc2[4][10];
#pragma unroll
    for (int i = 0; i < 4; i++)
#pragma unroll
        for (int j = 0; j < 10; j++) acc2[i][j] = 0ull;

    // per-thread query stats partials
    float4 s4  = make_float4(0.f, 0.f, 0.f, 0.f);
    float4 ss4 = make_float4(0.f, 0.f, 0.f, 0.f);

    for (int kb = 0; kb < NC; kb += KB) {
        // stage Q chunk: 32 x 64 floats = 512 float4 (2 per thread) + stats
#pragma unroll
        for (int i = 0; i < 2; i++) {
            int idx4 = tid + i * 256;
            int row = idx4 >> 4, col = (idx4 & 15) * 4;
            float4 v = *(const float4*)&qry[(size_t)(kb + row) * HW + m0 + col];
            *(float4*)&sQ[row][col] = v;
            s4.x += v.x; s4.y += v.y; s4.z += v.z; s4.w += v.w;
            ss4.x += v.x * v.x; ss4.y += v.y * v.y;
            ss4.z += v.z * v.z; ss4.w += v.w * v.w;
        }
        // stage P chunk: 32 x 320 floats = 2560 float4 (10 per thread)
#pragma unroll
        for (int i = 0; i < 10; i++) {
            int idx4 = tid + i * 256;
            int k  = idx4 / 80;
            int pp = (idx4 - k * 80) * 4;
            *(float4*)&sP[k][pp] =
                *(const float4*)&g_pnT[(size_t)(kb + k) * NP + pp];
        }
        __syncthreads();

#pragma unroll 8
        for (int k = 0; k < KB; k++) {
            float4 a = *(const float4*)&sQ[k][my * 4];
            unsigned long long a0, a1, a2, a3;
            asm("mov.b64 %0, {%1, %1};" : "=l"(a0) : "f"(a.x));
            asm("mov.b64 %0, {%1, %1};" : "=l"(a1) : "f"(a.y));
            asm("mov.b64 %0, {%1, %1};" : "=l"(a2) : "f"(a.z));
            asm("mov.b64 %0, {%1, %1};" : "=l"(a3) : "f"(a.w));
#pragma unroll
            for (int j4 = 0; j4 < 5; j4++) {
                ulonglong2 b2 = *(const ulonglong2*)&sP[k][nx * 4 + j4 * 64];
                // group by shared b -> slot-2 .reuse -> lower RF-bank rt
                asm("fma.rn.f32x2 %0, %1, %2, %0;" : "+l"(acc2[0][j4*2  ]) : "l"(a0), "l"(b2.x));
                asm("fma.rn.f32x2 %0, %1, %2, %0;" : "+l"(acc2[1][j4*2  ]) : "l"(a1), "l"(b2.x));
                asm("fma.rn.f32x2 %0, %1, %2, %0;" : "+l"(acc2[2][j4*2  ]) : "l"(a2), "l"(b2.x));
                asm("fma.rn.f32x2 %0, %1, %2, %0;" : "+l"(acc2[3][j4*2  ]) : "l"(a3), "l"(b2.x));
                asm("fma.rn.f32x2 %0, %1, %2, %0;" : "+l"(acc2[0][j4*2+1]) : "l"(a0), "l"(b2.y));
                asm("fma.rn.f32x2 %0, %1, %2, %0;" : "+l"(acc2[1][j4*2+1]) : "l"(a1), "l"(b2.y));
                asm("fma.rn.f32x2 %0, %1, %2, %0;" : "+l"(acc2[2][j4*2+1]) : "l"(a2), "l"(b2.y));
                asm("fma.rn.f32x2 %0, %1, %2, %0;" : "+l"(acc2[3][j4*2+1]) : "l"(a3), "l"(b2.y));
            }
        }
        __syncthreads();
    }

    // ---- query-stat reduction (reuse sP memory; all compute reads done) ----
    float2* pr  = (float2*)&sP[0][0];          // [16 rowg][16 colg][4 px] float2
    float*  sqi = (float*)((char*)pr + 8192);  // 64 floats: qinv*TAU per pixel
    {
        int base = (my * 16 + nx) * 4;
        pr[base + 0] = make_float2(s4.x, ss4.x);
        pr[base + 1] = make_float2(s4.y, ss4.y);
        pr[base + 2] = make_float2(s4.z, ss4.z);
        pr[base + 3] = make_float2(s4.w, ss4.w);
    }
    __syncthreads();
    if (tid < 64) {
        int cg = tid >> 2, j = tid & 3;
        float s = 0.f, ss = 0.f;
#pragma unroll
        for (int r = 0; r < 16; r++) {
            float2 t = pr[(r * 16 + cg) * 4 + j];
            s += t.x; ss += t.y;
        }
        float var = ss - s * s * (1.0f / 256.0f);
        sqi[tid] = TAUF / fmaxf(sqrtf(fmaxf(var, 0.f)), EPSF);
    }
    __syncthreads();

    // ---- epilogue: scale, softmax-weighted mean (== pred_grid), argmax ----
    // pair j2 = j4*2+h holds protos nx*4 + j4*64 + h*2 + {0,1};
    // d[j], j=j2*2+bit -> pidx = nx*4 + (j>>2)*64 + (j&3), ascending in j.
#pragma unroll
    for (int ii = 0; ii < 4; ii++) {
        int m = m0 + my * 4 + ii;
        float sc = sqi[my * 4 + ii];

        float d[20];
#pragma unroll
        for (int j2 = 0; j2 < 10; j2++) {
            float lo, hi;
            asm("mov.b64 {%0, %1}, %2;" : "=f"(lo), "=f"(hi) : "l"(acc2[ii][j2]));
            d[j2 * 2 + 0] = lo * sc;
            d[j2 * 2 + 1] = hi * sc;
        }
        float vmax = -1e30f; int vidx = 0;
#pragma unroll
        for (int j = 0; j < 20; j++) {
            int pidx = nx * 4 + (j >> 2) * 64 + (j & 3);
            if (d[j] > vmax) { vmax = d[j]; vidx = pidx; }
        }
#pragma unroll
        for (int o = 8; o; o >>= 1) {
            float om = __shfl_xor_sync(0xffffffffu, vmax, o, 16);
            int   oi = __shfl_xor_sync(0xffffffffu, vidx, o, 16);
            if (om > vmax || (om == vmax && oi < vidx)) { vmax = om; vidx = oi; }
        }
        float se = 0.f, sn = 0.f;
#pragma unroll
        for (int j = 0; j < 20; j++) {
            float e = __expf(d[j] - vmax);
            se += e; sn += e * d[j];
        }
#pragma unroll
        for (int o = 8; o; o >>= 1) {
            se += __shfl_xor_sync(0xffffffffu, se, o, 16);
            sn += __shfl_xor_sync(0xffffffffu, sn, o, 16);
        }
        if (nx == 0) {
            out[m]      = sn / se;        // pred_grid
            out[HW + m] = (float)vidx;    // debug_assign
        }
    }
}

// ---------------------------------------------------------------------------
extern "C" void kernel_launch(void* const* d_in, const int* in_sizes, int n_in,
                              void* d_out, int out_size)
{
    const float* qry = (const float*)d_in[0];   // (1,1,256,128,128)
    const float* sup = (const float*)d_in[1];   // (1,5,1,256,128,128)
    // d_in[2] (sup_y) and d_in[3] (thresh) are dead in the reference.
    float* out = (float*)d_out;                 // [pred_grid | debug_assign]

    pool_kernel<<<dim3(256, 5), 256>>>(sup);
    proto_norm_kernel<<<320, 256>>>();
    main_kernel<<<256, 256>>>(qry, out);
}